// round 14
// baseline (speedup 1.0000x reference)
#include <cuda_runtime.h>
#include <cuda_fp16.h>
#include <cstdint>

// B=1024, F=16, D=64, P=120
// out[b,p,k] = sum_{a,c} xi[b,a]*xj[b,c]*W[p,k,a*64+c] + bias[p,k]
// Per (p, b-tile): C[128,64] = Z[128,4096] @ W_p[64,4096]^T via mma.m16n8k16.f16 (f32 acc).
// R14: 3 CTAs/SM. xj moved from registers (32 regs in R11) to SMEM in a
// pre-packed per-fragment layout (1 LDS.64 per A-fragment pair, 160B stride =
// conflict-free) -> live set fits 84 regs without spills. fp16 xi tile,
// 3-slot ring (distance-2 prefetch), half-CTA named barriers, 24 warps/SM.

#define PDIM 120
#define OUT_ROW (PDIM * 64)
#define WELEMS (120 * 64 * 4096)

__device__ __half d_Wh[WELEMS];   // 62.9 MB fp16 W scratch (fragment-interleaved)

// ---- SMEM layout (bytes) ----
#define XIROWB 144                       // xi row stride (72 halfs; conflict-free)
#define OFF_XI 0                         // 128 * 144 = 18432 B
#define XJROWB 160                       // xjs row stride: (20g+q)%16 distinct
#define OFF_XJS (128 * XIROWB)           // 18432; 128*160 = 20480 B
#define OFF_BIAS_B (OFF_XJS + 128 * XJROWB)  // 38912: 64 f32 = 256 B
#define OFF_WS_B (OFF_BIAS_B + 256)      // 39168 (128-aligned)
#define WROWB 160                        // W stage row stride (128 data + 32 pad)
#define STAGE_B (64 * WROWB)             // 10240 B
#define NSTAGE 3
#define SM_BYTES (OFF_WS_B + NSTAGE * STAGE_B)  // 69888 B -> 3 CTAs/SM

__device__ __forceinline__ void cp16(uint32_t dst, const void* src) {
    asm volatile("cp.async.cg.shared.global [%0], [%1], 16;" :: "r"(dst), "l"(src));
}
__device__ __forceinline__ uint32_t smem_u32(const void* p) {
    uint32_t a;
    asm("{ .reg .u64 t; cvta.to.shared.u64 t, %1; cvt.u32.u64 %0, t; }" : "=r"(a) : "l"(p));
    return a;
}
__device__ __forceinline__ void mma16(float* d,
                                      uint32_t a0, uint32_t a1, uint32_t a2, uint32_t a3,
                                      uint32_t b0, uint32_t b1) {
    asm volatile(
        "mma.sync.aligned.m16n8k16.row.col.f32.f16.f16.f32 "
        "{%0,%1,%2,%3},{%4,%5,%6,%7},{%8,%9},{%0,%1,%2,%3};"
        : "+f"(d[0]), "+f"(d[1]), "+f"(d[2]), "+f"(d[3])
        : "r"(a0), "r"(a1), "r"(a2), "r"(a3), "r"(b0), "r"(b1));
}
__device__ __forceinline__ uint32_t h2u(__half2 h) { return *(uint32_t*)&h; }

// ---- W fp32 -> fp16 convert with fragment interleave: one 16-k group per thread ----
// out 32B = [k0 k1 k8 k9 | k2 k3 k10 k11 | k4 k5 k12 k13 | k6 k7 k14 k15]
__global__ __launch_bounds__(256)
void convert_W_kernel(const float* __restrict__ W)
{
    const size_t g = (size_t)blockIdx.x * 256 + threadIdx.x;  // 16-k group index
    const float* src = W + g * 16;
    const float4 v0 = *(const float4*)(src + 0);    // k0..3
    const float4 v1 = *(const float4*)(src + 4);    // k4..7
    const float4 v2 = *(const float4*)(src + 8);    // k8..11
    const float4 v3 = *(const float4*)(src + 12);   // k12..15

    uint4 o0, o1;
    o0.x = h2u(__floats2half2_rn(v0.x, v0.y));   // k0 k1
    o0.y = h2u(__floats2half2_rn(v2.x, v2.y));   // k8 k9
    o0.z = h2u(__floats2half2_rn(v0.z, v0.w));   // k2 k3
    o0.w = h2u(__floats2half2_rn(v2.z, v2.w));   // k10 k11
    o1.x = h2u(__floats2half2_rn(v1.x, v1.y));   // k4 k5
    o1.y = h2u(__floats2half2_rn(v3.x, v3.y));   // k12 k13
    o1.z = h2u(__floats2half2_rn(v1.z, v1.w));   // k6 k7
    o1.w = h2u(__floats2half2_rn(v3.z, v3.w));   // k14 k15

    uint4* dst = (uint4*)(d_Wh + g * 16);
    dst[0] = o0;
    dst[1] = o1;
}

__global__ __launch_bounds__(256, 3)
void op_fp16_kernel(const float* __restrict__ x,
                    const float* __restrict__ bias,
                    float* __restrict__ out)
{
    extern __shared__ __align__(16) char smc[];
    const int tid  = threadIdx.x;
    const int lane = tid & 31;
    const int wid  = tid >> 5;
    const int warpM = wid & 3;    // 4 x 32 rows = 128 M
    const int warpN = wid >> 2;   // 2 x 32 cols = 64 N (== warp group id)
    const int p  = blockIdx.x >> 3;
    const int b0 = (blockIdx.x & 7) << 7;

    // pair (fi, fj) from triu_indices(16, k=1)
    int fi = 0, rem = p;
    while (rem >= 15 - fi) { rem -= 15 - fi; ++fi; }
    const int fj = fi + 1 + rem;

    // ---- one-time fills ----
    // xi tile as fp16 (coalesced)
    {
        const int r = tid >> 1, hh = tid & 1;   // row, 32-col half
        const float* g = x + (size_t)(b0 + r) * 1024 + fi * 64 + hh * 32;
        char* dstRow = smc + OFF_XI + r * XIROWB + hh * 64;
        #pragma unroll
        for (int j = 0; j < 8; ++j) {
            const float4 v = *(const float4*)(g + j * 4);
            uint2 u;
            u.x = h2u(__floats2half2_rn(v.x, v.y));
            u.y = h2u(__floats2half2_rn(v.z, v.w));
            *(uint2*)(dstRow + j * 8) = u;
        }
    }
    // xjs: pre-packed A-fragment layout. xjs[r][j][kq] (8B) =
    //   half2(xj[r][j*16+kq*2], +1), half2(xj[r][j*16+kq*2+8], +9)
    {
        const int r = tid >> 1, hh = tid & 1;   // thread covers j = 2hh, 2hh+1
        const float* xr = x + (size_t)(b0 + r) * 1024 + fj * 64;
        char* dstRow = smc + OFF_XJS + r * XJROWB;
        #pragma unroll
        for (int jj = 0; jj < 2; ++jj) {
            const int j = hh * 2 + jj;
            #pragma unroll
            for (int kq = 0; kq < 4; ++kq) {
                const int c0 = j * 16 + kq * 2;
                const float2 u = *(const float2*)&xr[c0];
                const float2 v = *(const float2*)&xr[c0 + 8];
                uint2 w;
                w.x = h2u(__floats2half2_rn(u.x, u.y));
                w.y = h2u(__floats2half2_rn(v.x, v.y));
                *(uint2*)(dstRow + j * 32 + kq * 8) = w;
            }
        }
    }
    if (tid < 16)
        *(float4*)(smc + OFF_BIAS_B + tid * 16) = *(const float4*)(bias + p * 64 + tid * 4);

    const __half* Wp = d_Wh + (size_t)p * (64 * 4096);
    const uint32_t wsb = smem_u32(smc) + OFF_WS_B;
    const char* wsmc = smc + OFF_WS_B;

    // cp.async mapping: row wn = tid>>2 (0..63), quarter wq = tid&3 -> 2x16B.
    // Warps 0-3 write rows 0-31 = what warpN=0 reads; warps 4-7 rows 32-63 for
    // warpN=1: staging halves independent -> half-CTA named barriers.
    const int wn = tid >> 2, wq = tid & 3;
    const __half* wg = Wp + (size_t)wn * 4096;             // row of 4096 halfs
    const uint32_t wdst = wsb + (uint32_t)(wn * WROWB);

    // prologue: stages 0,1 -> slots 0,1 (one commit group each)
    #pragma unroll
    for (int st = 0; st < 2; ++st) {
        cp16(wdst + (uint32_t)st * STAGE_B + wq * 16, wg + st * 64 + wq * 8);
        cp16(wdst + (uint32_t)st * STAGE_B + (wq + 4) * 16, wg + st * 64 + (wq + 4) * 8);
        asm volatile("cp.async.commit_group;" ::: "memory");
    }

    float acc[2][4][4];
    #pragma unroll
    for (int mt = 0; mt < 2; ++mt)
        #pragma unroll
        for (int nt = 0; nt < 4; ++nt)
            #pragma unroll
            for (int q = 0; q < 4; ++q) acc[mt][nt][q] = 0.0f;

    const int rb = warpM * 32 + (lane >> 2);   // A row base (m=0)
    const int nb = warpN * 32 + (lane >> 2);   // B col base (nt=0)
    const int kq = lane & 3;

    const char* xi_c  = smc + OFF_XI + rb * XIROWB;
    const char* xjs_c = smc + OFF_XJS + rb * XJROWB + kq * 8;
    const int bOff = nb * WROWB + kq * 8;
    const int barid = 1 + warpN;   // named barrier per independent warp group

    __syncthreads();   // xi/xjs/bias tiles visible to both groups

    int slot = 0;   // ring slot of the stage being consumed

    // ---- main loop: 64 stages of K=64 (stage s == a index s) ----
    #pragma unroll 1
    for (int s = 0; s < 64; ++s) {
        // stage s landed when <=1 newer group pends
        asm volatile("cp.async.wait_group 1;" ::: "memory");
        asm volatile("bar.sync %0, 128;" :: "r"(barid) : "memory");

        // prefetch stage s+2 into slot (slot+2)%3 (held stage s-1: consumed)
        if (s < 62) {
            const int st = s + 2;
            const int wslot = (slot + 2 >= 3) ? slot - 1 : slot + 2;
            const uint32_t d = wdst + (uint32_t)wslot * STAGE_B;
            cp16(d + wq * 16, wg + st * 64 + wq * 8);
            cp16(d + (wq + 4) * 16, wg + st * 64 + (wq + 4) * 8);
        }
        asm volatile("cp.async.commit_group;" ::: "memory");

        const char* wsp = wsmc + slot * STAGE_B + bOff;

        __half2 xiv[4];
        #pragma unroll
        for (int m = 0; m < 4; ++m) {
            const __half hv = *(const __half*)(xi_c + m * 8 * XIROWB + s * 2);
            xiv[m] = __half2half2(hv);
        }

        #pragma unroll
        for (int j = 0; j < 4; ++j) {           // 4 k-steps of 16
            // A-side xj fragments: 4x LDS.64 (pre-packed), conflict-free
            uint2 xjf[4];
            #pragma unroll
            for (int m = 0; m < 4; ++m)
                xjf[m] = *(const uint2*)(xjs_c + m * 8 * XJROWB + j * 32);

            // B fragments for all 4 n-tiles: 4x LDS.64
            uint2 bb[4];
            #pragma unroll
            for (int nt = 0; nt < 4; ++nt)
                bb[nt] = *(const uint2*)(wsp + nt * 8 * WROWB + j * 32);

            uint32_t ah0[4], ah1[4];
            #pragma unroll
            for (int m = 0; m < 4; ++m) {
                ah0[m] = h2u(__hmul2(xiv[m], *(__half2*)&xjf[m].x));
                ah1[m] = h2u(__hmul2(xiv[m], *(__half2*)&xjf[m].y));
            }

            #pragma unroll
            for (int nt = 0; nt < 4; ++nt) {
                mma16(acc[0][nt], ah0[0], ah0[1], ah1[0], ah1[1], bb[nt].x, bb[nt].y);
                mma16(acc[1][nt], ah0[2], ah0[3], ah1[2], ah1[3], bb[nt].x, bb[nt].y);
            }
        }

        slot = (slot >= 2) ? 0 : slot + 1;
    }

    // ---- epilogue: bias + store ----
    const float* bias_s = (const float*)(smc + OFF_BIAS_B);
    const int colb = warpN * 32 + kq * 2;
    #pragma unroll
    for (int mt = 0; mt < 2; ++mt) {
        const int r_ = b0 + warpM * 32 + mt * 16 + (lane >> 2);
        float* o0 = out + (size_t)r_ * OUT_ROW + p * 64;
        float* o1 = out + (size_t)(r_ + 8) * OUT_ROW + p * 64;
        #pragma unroll
        for (int nt = 0; nt < 4; ++nt) {
            const int cl = colb + nt * 8;
            const float bz0 = bias_s[cl];
            const float bz1 = bias_s[cl + 1];
            float2 v0, v1;
            v0.x = acc[mt][nt][0] + bz0; v0.y = acc[mt][nt][1] + bz1;
            v1.x = acc[mt][nt][2] + bz0; v1.y = acc[mt][nt][3] + bz1;
            *(float2*)(o0 + cl) = v0;
            *(float2*)(o1 + cl) = v1;
        }
    }
}

extern "C" void kernel_launch(void* const* d_in, const int* in_sizes, int n_in,
                              void* d_out, int out_size)
{
    const float* x    = (const float*)d_in[0];   // (1024, 16, 64)
    const float* W    = (const float*)d_in[1];   // (120, 64, 4096)
    const float* bias = (const float*)d_in[2];   // (120, 64)
    float* out = (float*)d_out;                  // (1024, 120, 64)

    // 1) W -> fp16 scratch, fragment-interleaved (1 group of 16 per thread)
    convert_W_kernel<<<WELEMS / (256 * 16), 256>>>(W);

    // 2) main GEMM
    cudaFuncSetAttribute(op_fp16_kernel,
                         cudaFuncAttributeMaxDynamicSharedMemorySize, SM_BYTES);
    op_fp16_kernel<<<PDIM * 8, 256, SM_BYTES>>>(x, bias, out);
}

// round 15
// speedup vs baseline: 1.2239x; 1.2239x over previous
#include <cuda_runtime.h>
#include <cuda_fp16.h>
#include <cstdint>

// B=1024, F=16, D=64, P=120
// out[b,p,k] = sum_{a,c} xi[b,a]*xj[b,c]*W[p,k,a*64+c] + bias[p,k]
// Per (p, b-tile): C[128,64] = Z[128,4096] @ W_p[64,4096]^T via mma.m16n8k16.f16 (f32 acc).
// R15 = R11 GEMM (6-slot ring, 2 stages/iter, half-CTA named barriers,
// fragment-interleaved W, register xj) with the W->fp16 convert FUSED into the
// main kernel: the 8 CTAs of each p cooperatively convert W_p (8 k-rows each),
// then sync on a per-p global arrive/spin counter. Later-p conversion overlaps
// earlier-p GEMM instead of running as a serial 27us prologue kernel.

#define PDIM 120
#define OUT_ROW (PDIM * 64)
#define WELEMS (120 * 64 * 4096)

__device__ __half d_Wh[WELEMS];   // 62.9 MB fp16 W scratch (fragment-interleaved)
__device__ int d_cnt[PDIM];       // per-p arrive/depart counters (self-resetting)

// ---- SMEM layout ----
#define XST 68                           // xi row stride (floats)
#define OFF_XI 0                         // xi[128][68] f32 = 34816 B
#define OFF_BIAS (128 * XST)             // 64 f32
#define OFF_WS_B ((OFF_BIAS + 64) * 4)   // 35072 B (16B aligned)
#define WROWB 160                        // stage row stride bytes (128 data + 32 pad)
#define STAGE_B (64 * WROWB)             // 10240 B
#define NSTAGE 6
#define SM_BYTES (OFF_WS_B + NSTAGE * STAGE_B)  // 96512 B -> 2 CTAs/SM

__device__ __forceinline__ void cp16(uint32_t dst, const void* src) {
    asm volatile("cp.async.cg.shared.global [%0], [%1], 16;" :: "r"(dst), "l"(src));
}
__device__ __forceinline__ uint32_t smem_u32(const void* p) {
    uint32_t a;
    asm("{ .reg .u64 t; cvta.to.shared.u64 t, %1; cvt.u32.u64 %0, t; }" : "=r"(a) : "l"(p));
    return a;
}
__device__ __forceinline__ void mma16(float* d,
                                      uint32_t a0, uint32_t a1, uint32_t a2, uint32_t a3,
                                      uint32_t b0, uint32_t b1) {
    asm volatile(
        "mma.sync.aligned.m16n8k16.row.col.f32.f16.f16.f32 "
        "{%0,%1,%2,%3},{%4,%5,%6,%7},{%8,%9},{%0,%1,%2,%3};"
        : "+f"(d[0]), "+f"(d[1]), "+f"(d[2]), "+f"(d[3])
        : "r"(a0), "r"(a1), "r"(a2), "r"(a3), "r"(b0), "r"(b1));
}
__device__ __forceinline__ uint32_t h2u(__half2 h) { return *(uint32_t*)&h; }

__global__ __launch_bounds__(256, 2)
void op_fp16_kernel(const float* __restrict__ x,
                    const float* __restrict__ W,
                    const float* __restrict__ bias,
                    float* __restrict__ out)
{
    extern __shared__ __align__(16) float sm[];
    const int tid  = threadIdx.x;
    const int lane = tid & 31;
    const int wid  = tid >> 5;
    const int warpM = wid & 3;    // 4 x 32 rows = 128 M
    const int warpN = wid >> 2;   // 2 x 32 cols = 64 N (== warp group id)
    const int p     = blockIdx.x >> 3;
    const int slice = blockIdx.x & 7;
    const int b0    = slice << 7;

    // ---- fused W convert: this CTA converts k-rows [slice*8, slice*8+8) of W_p
    // into fragment-interleaved fp16. 16-k group layout:
    // out 32B = [k0 k1 k8 k9 | k2 k3 k10 k11 | k4 k5 k12 k13 | k6 k7 k14 k15]
    {
        const size_t gBase = (size_t)p * 16384 + (size_t)slice * 2048;  // 16-k groups
        #pragma unroll
        for (int k8 = 0; k8 < 8; ++k8) {
            const size_t g = gBase + (size_t)(k8 * 256 + tid);
            const float* src = W + g * 16;
            const float4 v0 = *(const float4*)(src + 0);
            const float4 v1 = *(const float4*)(src + 4);
            const float4 v2 = *(const float4*)(src + 8);
            const float4 v3 = *(const float4*)(src + 12);
            uint4 o0, o1;
            o0.x = h2u(__floats2half2_rn(v0.x, v0.y));
            o0.y = h2u(__floats2half2_rn(v2.x, v2.y));
            o0.z = h2u(__floats2half2_rn(v0.z, v0.w));
            o0.w = h2u(__floats2half2_rn(v2.z, v2.w));
            o1.x = h2u(__floats2half2_rn(v1.x, v1.y));
            o1.y = h2u(__floats2half2_rn(v3.x, v3.y));
            o1.z = h2u(__floats2half2_rn(v1.z, v1.w));
            o1.w = h2u(__floats2half2_rn(v3.z, v3.w));
            uint4* dst = (uint4*)(d_Wh + g * 16);
            dst[0] = o0;
            dst[1] = o1;
        }
    }
    __syncthreads();            // all convert stores issued CTA-wide
    if (tid == 0) {
        __threadfence();        // release: stores visible at GPU scope
        atomicAdd(&d_cnt[p], 1);
    }

    // pair (fi, fj) from triu_indices(16, k=1)
    int fi = 0, rem = p;
    while (rem >= 15 - fi) { rem -= 15 - fi; ++fi; }
    const int fj = fi + 1 + rem;

    // ---- one-time fills (overlap the spin window): xi tile, bias ----
    {
        const int c4 = (tid & 15) * 4, r0 = tid >> 4;
        #pragma unroll
        for (int it = 0; it < 8; ++it) {
            const int row = r0 + it * 16;
            const float* g = x + (size_t)(b0 + row) * 1024 + fi * 64;
            *(float4*)&sm[OFF_XI + row * XST + c4] = *(const float4*)(g + c4);
        }
    }
    if (tid < 16)
        *(float4*)&sm[OFF_BIAS + tid * 4] = *(const float4*)(bias + p * 64 + tid * 4);

    const int rb = warpM * 32 + (lane >> 2);   // A row base (m=0)
    const int nb = warpN * 32 + (lane >> 2);   // B col base (nt=0)
    const int kq = lane & 3;

    // ---- xj -> registers as packed half2, straight from global (one-time) ----
    __half2 xjh[4][8];
    #pragma unroll
    for (int m = 0; m < 4; ++m) {
        const float* xr = x + (size_t)(b0 + rb + m * 8) * 1024 + fj * 64;
        #pragma unroll
        for (int j = 0; j < 4; ++j) {
            const float2 u = *(const float2*)&xr[j * 16 + kq * 2];
            const float2 v = *(const float2*)&xr[j * 16 + kq * 2 + 8];
            xjh[m][2 * j]     = __floats2half2_rn(u.x, u.y);
            xjh[m][2 * j + 1] = __floats2half2_rn(v.x, v.y);
        }
    }

    // ---- wait for all 8 CTAs of this p to finish converting W_p ----
    if (tid == 0) {
        int v;
        do {
            asm volatile("ld.global.acquire.gpu.b32 %0, [%1];"
                         : "=r"(v) : "l"(&d_cnt[p]) : "memory");
            if (v >= 8) break;
            __nanosleep(128);
        } while (true);
        // depart: counter 8->16; the 16th increment (old==15) resets to 0,
        // leaving the counter at 0 for the next graph replay.
        const int d = atomicAdd(&d_cnt[p], 1);
        if (d == 15) atomicExch(&d_cnt[p], 0);
    }
    __syncthreads();   // releases the CTA; also publishes xi/bias tiles

    const __half* Wp = d_Wh + (size_t)p * (64 * 4096);
    const uint32_t wsb = smem_u32(sm) + OFF_WS_B;
    const char* wsmc = (const char*)sm + OFF_WS_B;

    // cp.async mapping: row wn = tid>>2 (0..63), quarter wq = tid&3 -> 2x16B.
    // Warps 0-3 write rows 0-31 = what warpN=0 reads; warps 4-7 rows 32-63 for
    // warpN=1. Staging halves independent -> half-CTA named barriers.
    const int wn = tid >> 2, wq = tid & 3;
    const __half* wg = Wp + (size_t)wn * 4096;             // row of 4096 halfs
    const uint32_t wdst = wsb + (uint32_t)(wn * WROWB);

    // prologue: stages 0..3 as 2 groups of 2 stages
    #pragma unroll
    for (int gidx = 0; gidx < 2; ++gidx) {
        #pragma unroll
        for (int h = 0; h < 2; ++h) {
            const int st = gidx * 2 + h;
            cp16(wdst + (uint32_t)st * STAGE_B + wq * 16, wg + st * 64 + wq * 8);
            cp16(wdst + (uint32_t)st * STAGE_B + (wq + 4) * 16, wg + st * 64 + (wq + 4) * 8);
        }
        asm volatile("cp.async.commit_group;" ::: "memory");
    }

    float acc[2][4][4];
    #pragma unroll
    for (int mt = 0; mt < 2; ++mt)
        #pragma unroll
        for (int nt = 0; nt < 4; ++nt)
            #pragma unroll
            for (int q = 0; q < 4; ++q) acc[mt][nt][q] = 0.0f;

    const float* xi_b = sm + OFF_XI + rb * XST;
    const int bOff = nb * WROWB + kq * 8;
    const int barid = 1 + warpN;   // named barrier per independent warp group

    int slotA = 0;   // ring slot of the even stage being consumed (0, 2, 4)

    // ---- main loop: 32 iterations x 2 stages of K=64 (stage s == a index s) ----
    #pragma unroll 1
    for (int it = 0; it < 32; ++it) {
        // group `it` (stages 2it, 2it+1) is complete when <=1 newer group pends
        asm volatile("cp.async.wait_group 1;" ::: "memory");
        asm volatile("bar.sync %0, 128;" :: "r"(barid) : "memory");

        // prefetch group it+2 (stages 2it+4, 2it+5) into slots slotA+4, slotA+5 (mod 6)
        if (it < 30) {
            const int st = 2 * it + 4;
            const int wslotA = (slotA >= 2) ? slotA - 2 : slotA + 4;
            const uint32_t d0 = wdst + (uint32_t)wslotA * STAGE_B;
            const uint32_t d1 = d0 + STAGE_B;
            cp16(d0 + wq * 16, wg + st * 64 + wq * 8);
            cp16(d0 + (wq + 4) * 16, wg + st * 64 + (wq + 4) * 8);
            cp16(d1 + wq * 16, wg + (st + 1) * 64 + wq * 8);
            cp16(d1 + (wq + 4) * 16, wg + (st + 1) * 64 + (wq + 4) * 8);
        }
        asm volatile("cp.async.commit_group;" ::: "memory");

        #pragma unroll
        for (int h = 0; h < 2; ++h) {
            const int s = 2 * it + h;
            const char* wsp = wsmc + (slotA + h) * STAGE_B + bOff;

            __half2 xiv[4];
            #pragma unroll
            for (int m = 0; m < 4; ++m)
                xiv[m] = __float2half2_rn(xi_b[m * 8 * XST + s]);

            #pragma unroll
            for (int j = 0; j < 4; ++j) {           // 4 k-steps of 16
                uint2 bb[4];
                #pragma unroll
                for (int nt = 0; nt < 4; ++nt)
                    bb[nt] = *(const uint2*)(wsp + nt * 8 * WROWB + j * 32);

                uint32_t ah0[4], ah1[4];
                #pragma unroll
                for (int m = 0; m < 4; ++m) {
                    ah0[m] = h2u(__hmul2(xiv[m], xjh[m][2 * j]));
                    ah1[m] = h2u(__hmul2(xiv[m], xjh[m][2 * j + 1]));
                }

                #pragma unroll
                for (int nt = 0; nt < 4; ++nt) {
                    mma16(acc[0][nt], ah0[0], ah0[1], ah1[0], ah1[1], bb[nt].x, bb[nt].y);
                    mma16(acc[1][nt], ah0[2], ah0[3], ah1[2], ah1[3], bb[nt].x, bb[nt].y);
                }
            }
        }

        slotA = (slotA >= 4) ? 0 : slotA + 2;
    }

    // ---- epilogue: bias + store ----
    const int colb = warpN * 32 + kq * 2;
    #pragma unroll
    for (int mt = 0; mt < 2; ++mt) {
        const int r_ = b0 + warpM * 32 + mt * 16 + (lane >> 2);
        float* o0 = out + (size_t)r_ * OUT_ROW + p * 64;
        float* o1 = out + (size_t)(r_ + 8) * OUT_ROW + p * 64;
        #pragma unroll
        for (int nt = 0; nt < 4; ++nt) {
            const int cl = colb + nt * 8;
            const float bz0 = sm[OFF_BIAS + cl];
            const float bz1 = sm[OFF_BIAS + cl + 1];
            float2 v0, v1;
            v0.x = acc[mt][nt][0] + bz0; v0.y = acc[mt][nt][1] + bz1;
            v1.x = acc[mt][nt][2] + bz0; v1.y = acc[mt][nt][3] + bz1;
            *(float2*)(o0 + cl) = v0;
            *(float2*)(o1 + cl) = v1;
        }
    }
}

extern "C" void kernel_launch(void* const* d_in, const int* in_sizes, int n_in,
                              void* d_out, int out_size)
{
    const float* x    = (const float*)d_in[0];   // (1024, 16, 64)
    const float* W    = (const float*)d_in[1];   // (120, 64, 4096)
    const float* bias = (const float*)d_in[2];   // (120, 64)
    float* out = (float*)d_out;                  // (1024, 120, 64)

    cudaFuncSetAttribute(op_fp16_kernel,
                         cudaFuncAttributeMaxDynamicSharedMemorySize, SM_BYTES);
    // 120 p x 8 b-tiles; p-major. Fused convert: each p-group of 8 CTAs
    // converts its own W_p before the GEMM (per-p global counter sync).
    op_fp16_kernel<<<PDIM * 8, 256, SM_BYTES>>>(x, W, bias, out);
}